// round 2
// baseline (speedup 1.0000x reference)
#include <cuda_runtime.h>
#include <stdint.h>

// SpikeFP8Adder_Spatial: soft-logic E4M3 adder on {0,1}-valued float bit vectors.
// Exact 0/1 inputs => the gate network collapses to integer bit logic.
// Pure HBM-bound (384 MB traffic). This version: 2 rows/thread (strided halves)
// for 8 front-batched loads per thread, plus streaming cache hints.

struct Row { uint4 lo, hi; };

__device__ __forceinline__ void fp8add_row(
    const uint4& a0, const uint4& a1,
    const uint4& b0, const uint4& b1,
    uint4& o0, uint4& o1)
{
    // Pack MSB-first: index 0 -> bit7 ... index 7 -> bit0. 1.0f = 0x3F800000 (bit 23 set).
    unsigned pa =
        (((a0.x >> 23) & 1u) << 7) | (((a0.y >> 23) & 1u) << 6) |
        (((a0.z >> 23) & 1u) << 5) | (((a0.w >> 23) & 1u) << 4) |
        (((a1.x >> 23) & 1u) << 3) | (((a1.y >> 23) & 1u) << 2) |
        (((a1.z >> 23) & 1u) << 1) |  ((a1.w >> 23) & 1u);
    unsigned pb =
        (((b0.x >> 23) & 1u) << 7) | (((b0.y >> 23) & 1u) << 6) |
        (((b0.z >> 23) & 1u) << 5) | (((b0.w >> 23) & 1u) << 4) |
        (((b1.x >> 23) & 1u) << 3) | (((b1.y >> 23) & 1u) << 2) |
        (((b1.z >> 23) & 1u) << 1) |  ((b1.w >> 23) & 1u);

    unsigned sa = (pa >> 7) & 1u, ea = (pa >> 3) & 15u, ma = pa & 7u;
    unsigned sb = (pb >> 7) & 1u, eb = (pb >> 3) & 15u, mb = pb & 7u;

    // Comparator4: sel = (ea >= eb)
    bool sel = (ea >= eb);
    unsigned el = sel ? ea : eb;
    unsigned es = sel ? eb : ea;
    unsigned ml = sel ? ma : mb;
    unsigned ms = sel ? mb : ma;
    unsigned sl = sel ? sa : sb;
    unsigned ss = sel ? sb : sa;

    unsigned diff = el - es;

    // 12-bit extended mantissas: hidden at bit 10, mantissa at bits 9..7.
    unsigned extl = ((el != 0u) ? 0x400u : 0u) | (ml << 7);
    unsigned exts = (((es != 0u) ? 0x400u : 0u) | (ms << 7)) >> diff;

    // 12-bit add/sub with wrap (matches ripple carry/borrow mod 4096).
    unsigned mant = (sl == ss) ? ((extl + exts) & 0xFFFu)
                               : ((extl - exts) & 0xFFFu);

    unsigned top8 = mant >> 4;

    // LZD8: clz over 8 bits, saturating at 7 for zero input.
    unsigned lzc = top8 ? (unsigned)(__clz((int)top8) - 24) : 7u;

    unsigned norm = (top8 << lzc) & 0xFFu;

    // exp_new = (el - lzc + 1) mod 16
    unsigned en = (el - lzc + 1u) & 15u;

    const unsigned ONE = 0x3F800000u;
    o0.x = sl * ONE;
    o0.y = ((en >> 3) & 1u) * ONE;
    o0.z = ((en >> 2) & 1u) * ONE;
    o0.w = ((en >> 1) & 1u) * ONE;
    o1.x = (en & 1u) * ONE;
    o1.y = ((norm >> 6) & 1u) * ONE;
    o1.z = ((norm >> 5) & 1u) * ONE;
    o1.w = ((norm >> 4) & 1u) * ONE;
}

__global__ __launch_bounds__(256) void fp8add_kernel2(
    const uint4* __restrict__ A,
    const uint4* __restrict__ B,
    uint4* __restrict__ O,
    int half)   // nrows / 2
{
    int i = blockIdx.x * blockDim.x + threadIdx.x;
    if (i >= half) return;
    int j = i + half;

    // Front-batch all 8 loads (streaming, evict-first) for maximum MLP.
    uint4 a0 = __ldcs(&A[2 * i + 0]);
    uint4 a1 = __ldcs(&A[2 * i + 1]);
    uint4 b0 = __ldcs(&B[2 * i + 0]);
    uint4 b1 = __ldcs(&B[2 * i + 1]);
    uint4 c0 = __ldcs(&A[2 * j + 0]);
    uint4 c1 = __ldcs(&A[2 * j + 1]);
    uint4 d0 = __ldcs(&B[2 * j + 0]);
    uint4 d1 = __ldcs(&B[2 * j + 1]);

    uint4 o0, o1, p0, p1;
    fp8add_row(a0, a1, b0, b1, o0, o1);
    fp8add_row(c0, c1, d0, d1, p0, p1);

    __stcs(&O[2 * i + 0], o0);
    __stcs(&O[2 * i + 1], o1);
    __stcs(&O[2 * j + 0], p0);
    __stcs(&O[2 * j + 1], p1);
}

__global__ __launch_bounds__(256) void fp8add_kernel1(
    const uint4* __restrict__ A,
    const uint4* __restrict__ B,
    uint4* __restrict__ O,
    int nrows, int start)
{
    int i = start + blockIdx.x * blockDim.x + threadIdx.x;
    if (i >= nrows) return;
    uint4 a0 = __ldcs(&A[2 * i + 0]);
    uint4 a1 = __ldcs(&A[2 * i + 1]);
    uint4 b0 = __ldcs(&B[2 * i + 0]);
    uint4 b1 = __ldcs(&B[2 * i + 1]);
    uint4 o0, o1;
    fp8add_row(a0, a1, b0, b1, o0, o1);
    __stcs(&O[2 * i + 0], o0);
    __stcs(&O[2 * i + 1], o1);
}

extern "C" void kernel_launch(void* const* d_in, const int* in_sizes, int n_in,
                              void* d_out, int out_size)
{
    const uint4* A = (const uint4*)d_in[0];
    const uint4* B = (const uint4*)d_in[1];
    uint4* O = (uint4*)d_out;

    int nrows = in_sizes[0] / 8;
    int half = nrows >> 1;
    int threads = 256;

    if (half > 0) {
        int blocks = (half + threads - 1) / threads;
        fp8add_kernel2<<<blocks, threads>>>(A, B, O, half);
    }
    if (nrows & 1) {
        // odd tail row (not hit for N=4194304, kept for generality)
        fp8add_kernel1<<<1, 1>>>(A, B, O, nrows, nrows - 1);
    }
}